// round 16
// baseline (speedup 1.0000x reference)
#include <cuda_runtime.h>
#include <cuda_fp16.h>
#include <mma.h>
#include <cstdint>

using namespace nvcuda;

#define D_MODEL   512
#define NUM_RULES 16
#define BATCH     4
#define SEQ       4096
#define M_TOTAL   (BATCH * SEQ)          // 16384

#define BM 128
#define BN 128
#define BK 16
#define NTHREADS 256
#define KTILES          (D_MODEL / BK)   // 32
#define ROWBLOCKS       (M_TOTAL / BM)   // 128
#define ROWBLK_PER_B    (SEQ / BM)       // 32

// ---- static scratch (alloc-free; proven footprint) ----
__device__ float g_H[(size_t)M_TOTAL * D_MODEL];                 // 32 MB
__device__ float g_part[NUM_RULES * ROWBLOCKS * D_MODEL];        // 4 MB
__device__ float g_cond[BATCH * NUM_RULES * D_MODEL];            // 128 KB

__device__ __forceinline__ float sigmoidf_(float v) {
    return 1.0f / (1.0f + __expf(-v));
}
// split one fp32 pair into fp16 (hi, lo) pairs: x = hi + lo + O(2^-22 x)
__device__ __forceinline__ void split2(float x, float y, __half2& hi, __half2& lo) {
    hi = __floats2half2_rn(x, y);
    float2 hf = __half22float2(hi);
    lo = __floats2half2_rn(x - hf.x, y - hf.y);
}

// MODE 0: sigmoid col-sums -> g_part   MODE 1: g_H = silu(acc+b)
// MODE 2: OUT (+)= (acc+b) * cond
template <int MODE>
__global__ __launch_bounds__(NTHREADS, 2)
void rb_gemm(const float* __restrict__ Abase,
             const float* __restrict__ Wbase,
             const float* __restrict__ Bbase,
             float* __restrict__ OUT,
             int rule, int accumulate)
{
    const int r = (MODE == 0) ? (int)blockIdx.z : rule;
    const float* __restrict__ A    = (MODE == 2) ? g_H : Abase;
    const float* __restrict__ W    = Wbase + (size_t)r * D_MODEL * D_MODEL;   // [K][N] row-major
    const float* __restrict__ bias = Bbase + r * D_MODEL;

    const int tid = threadIdx.x;
    const int w = tid >> 5, lane = tid & 31;
    const int wm = w >> 1, wn = w & 1;           // warp grid 4(m) x 2(n); warp tile 32x64
    const int rowBase = blockIdx.y * BM;
    const int colBase = blockIdx.x * BN;

    // SMEM: fp16 hi/lo planes. A: [buf][plane][m][k] ldm=16; B: [buf][plane][k][n] ldm=128
    __shared__ __half Ah[2][2][BM][BK];          // 16 KB
    __shared__ __half Bh[2][2][BK][BN];          // 16 KB
    __shared__ float red[(MODE == 0) ? 4 : 1][BN];
    __shared__ float stg_s[8][256];              // per-warp 16x16 staging

    // global-load mapping (one K-tile): A 128x16, B 16x128; 8 fp32 per thread each
    const int aRow = tid >> 1, aC = (tid & 1) * 8;
    const int bRow = tid >> 4, bC = (tid & 15) * 8;
    const float* aPtr = A + (size_t)(rowBase + aRow) * D_MODEL + aC;
    const float* wPtr = W + (size_t)bRow * D_MODEL + colBase + bC;

    wmma::fragment<wmma::accumulator, 16, 16, 16, float> acc[2][4];
#pragma unroll
    for (int mf = 0; mf < 2; ++mf)
#pragma unroll
        for (int nf = 0; nf < 4; ++nf) wmma::fill_fragment(acc[mf][nf], 0.0f);

    float4 aReg[2], bReg[2];

    // prologue: tile 0 -> buf 0
    aReg[0] = *(const float4*)aPtr;       aReg[1] = *(const float4*)(aPtr + 4);
    bReg[0] = *(const float4*)wPtr;       bReg[1] = *(const float4*)(wPtr + 4);
    {
        const float av[8] = {aReg[0].x, aReg[0].y, aReg[0].z, aReg[0].w,
                             aReg[1].x, aReg[1].y, aReg[1].z, aReg[1].w};
        const float bv[8] = {bReg[0].x, bReg[0].y, bReg[0].z, bReg[0].w,
                             bReg[1].x, bReg[1].y, bReg[1].z, bReg[1].w};
#pragma unroll
        for (int i = 0; i < 4; ++i) {
            __half2 hi, lo;
            split2(av[2 * i], av[2 * i + 1], hi, lo);
            *(__half2*)&Ah[0][0][aRow][aC + 2 * i] = hi;
            *(__half2*)&Ah[0][1][aRow][aC + 2 * i] = lo;
            split2(bv[2 * i], bv[2 * i + 1], hi, lo);
            *(__half2*)&Bh[0][0][bRow][bC + 2 * i] = hi;
            *(__half2*)&Bh[0][1][bRow][bC + 2 * i] = lo;
        }
    }
    __syncthreads();

    for (int kt = 0; kt < KTILES; ++kt) {
        if (kt + 1 < KTILES) {
            const int k0 = (kt + 1) * BK;
            aReg[0] = *(const float4*)(aPtr + k0);
            aReg[1] = *(const float4*)(aPtr + k0 + 4);
            bReg[0] = *(const float4*)(wPtr + (size_t)k0 * D_MODEL);
            bReg[1] = *(const float4*)(wPtr + (size_t)k0 * D_MODEL + 4);
        }
        const int buf = kt & 1;
        // ---- tensor compute on buf: acc += Ahi*Bhi + Ahi*Blo + Alo*Bhi ----
#pragma unroll
        for (int mf = 0; mf < 2; ++mf) {
            wmma::fragment<wmma::matrix_a, 16, 16, 16, __half, wmma::row_major> a_hi, a_lo;
            wmma::load_matrix_sync(a_hi, &Ah[buf][0][wm * 32 + mf * 16][0], BK);
            wmma::load_matrix_sync(a_lo, &Ah[buf][1][wm * 32 + mf * 16][0], BK);
#pragma unroll
            for (int nf = 0; nf < 4; ++nf) {
                wmma::fragment<wmma::matrix_b, 16, 16, 16, __half, wmma::row_major> b_hi, b_lo;
                wmma::load_matrix_sync(b_hi, &Bh[buf][0][0][wn * 64 + nf * 16], BN);
                wmma::load_matrix_sync(b_lo, &Bh[buf][1][0][wn * 64 + nf * 16], BN);
                wmma::mma_sync(acc[mf][nf], a_hi, b_hi, acc[mf][nf]);
                wmma::mma_sync(acc[mf][nf], a_hi, b_lo, acc[mf][nf]);
                wmma::mma_sync(acc[mf][nf], a_lo, b_hi, acc[mf][nf]);
            }
        }
        if (kt + 1 < KTILES) {
            const int nb = buf ^ 1;
            const float av[8] = {aReg[0].x, aReg[0].y, aReg[0].z, aReg[0].w,
                                 aReg[1].x, aReg[1].y, aReg[1].z, aReg[1].w};
            const float bv[8] = {bReg[0].x, bReg[0].y, bReg[0].z, bReg[0].w,
                                 bReg[1].x, bReg[1].y, bReg[1].z, bReg[1].w};
#pragma unroll
            for (int i = 0; i < 4; ++i) {
                __half2 hi, lo;
                split2(av[2 * i], av[2 * i + 1], hi, lo);
                *(__half2*)&Ah[nb][0][aRow][aC + 2 * i] = hi;
                *(__half2*)&Ah[nb][1][aRow][aC + 2 * i] = lo;
                split2(bv[2 * i], bv[2 * i + 1], hi, lo);
                *(__half2*)&Bh[nb][0][bRow][bC + 2 * i] = hi;
                *(__half2*)&Bh[nb][1][bRow][bC + 2 * i] = lo;
            }
            __syncthreads();
        }
    }

    // ---- epilogue: stage each 16x16 accumulator through a per-warp smem slot ----
    float* stg = stg_s[w];
    const int erow = lane >> 1;                 // 0..15
    const int ecol = (lane & 1) * 8;            // 0 or 8

    float cs[4][8];
    if (MODE == 0) {
#pragma unroll
        for (int nf = 0; nf < 4; ++nf)
#pragma unroll
            for (int j = 0; j < 8; ++j) cs[nf][j] = 0.0f;
    }

#pragma unroll
    for (int mf = 0; mf < 2; ++mf) {
#pragma unroll
        for (int nf = 0; nf < 4; ++nf) {
            wmma::store_matrix_sync(stg, acc[mf][nf], 16, wmma::mem_row_major);
            __syncwarp();
            const float* rowp = stg + erow * 16 + ecol;
            const int col = colBase + wn * 64 + nf * 16 + ecol;
            if (MODE == 0) {
#pragma unroll
                for (int j = 0; j < 8; ++j)
                    cs[nf][j] += sigmoidf_(rowp[j] + __ldg(bias + col + j));
            } else if (MODE == 1) {
                const int row = rowBase + wm * 32 + mf * 16 + erow;
                float v[8];
#pragma unroll
                for (int j = 0; j < 8; ++j) {
                    const float z = rowp[j] + __ldg(bias + col + j);
                    v[j] = z * sigmoidf_(z);
                }
                float4* o = (float4*)&g_H[(size_t)row * D_MODEL + col];
                o[0] = make_float4(v[0], v[1], v[2], v[3]);
                o[1] = make_float4(v[4], v[5], v[6], v[7]);
            } else {
                const int row = rowBase + wm * 32 + mf * 16 + erow;
                const int b = rowBase / SEQ;
                const float* cbase = &g_cond[(size_t)(b * NUM_RULES + r) * D_MODEL];
                float v[8];
#pragma unroll
                for (int j = 0; j < 8; ++j)
                    v[j] = (rowp[j] + __ldg(bias + col + j)) * __ldg(cbase + col + j);
                float4* o = (float4*)&OUT[(size_t)row * D_MODEL + col];
                if (accumulate) {
                    float4 p0 = o[0], p1 = o[1];
                    v[0] += p0.x; v[1] += p0.y; v[2] += p0.z; v[3] += p0.w;
                    v[4] += p1.x; v[5] += p1.y; v[6] += p1.z; v[7] += p1.w;
                }
                o[0] = make_float4(v[0], v[1], v[2], v[3]);
                o[1] = make_float4(v[4], v[5], v[6], v[7]);
            }
            __syncwarp();
        }
    }

    if (MODE == 0) {
        // sum 16 same-parity lanes per column half (parity-preserving offsets)
#pragma unroll
        for (int nf = 0; nf < 4; ++nf)
#pragma unroll
            for (int j = 0; j < 8; ++j) {
                cs[nf][j] += __shfl_down_sync(0xFFFFFFFFu, cs[nf][j], 16);
                cs[nf][j] += __shfl_down_sync(0xFFFFFFFFu, cs[nf][j], 8);
                cs[nf][j] += __shfl_down_sync(0xFFFFFFFFu, cs[nf][j], 4);
                cs[nf][j] += __shfl_down_sync(0xFFFFFFFFu, cs[nf][j], 2);
            }
        if (lane < 2) {
#pragma unroll
            for (int nf = 0; nf < 4; ++nf)
#pragma unroll
                for (int j = 0; j < 8; ++j)
                    red[wm][wn * 64 + nf * 16 + lane * 8 + j] = cs[nf][j];
        }
        __syncthreads();
        if (tid < BN)
            g_part[((size_t)r * ROWBLOCKS + blockIdx.y) * D_MODEL + colBase + tid] =
                red[0][tid] + red[1][tid] + red[2][tid] + red[3][tid];
    }
}

// g_cond[b][r][d] = (1/SEQ) * sum over row-blocks of batch b
__global__ void reduce_cond_kernel() {
    const int i = blockIdx.x * blockDim.x + threadIdx.x;
    if (i >= BATCH * NUM_RULES * D_MODEL) return;
    const int d = i % D_MODEL;
    const int t = i / D_MODEL;
    const int r = t % NUM_RULES;
    const int b = t / NUM_RULES;
    float s = 0.0f;
    #pragma unroll 4
    for (int q = 0; q < ROWBLK_PER_B; ++q)
        s += g_part[((size_t)r * ROWBLOCKS + b * ROWBLK_PER_B + q) * D_MODEL + d];
    g_cond[i] = s * (1.0f / (float)SEQ);
}

extern "C" void kernel_launch(void* const* d_in, const int* in_sizes, int n_in,
                              void* d_out, int out_size) {
    const float* X   = (const float*)d_in[0];   // [4,4096,512]
    const float* Wc  = (const float*)d_in[1];   // [16,512,512]
    const float* bc  = (const float*)d_in[2];   // [16,512]
    const float* Wa1 = (const float*)d_in[3];
    const float* ba1 = (const float*)d_in[4];
    const float* Wa2 = (const float*)d_in[5];
    const float* ba2 = (const float*)d_in[6];
    float* out = (float*)d_out;
    (void)in_sizes; (void)n_in; (void)out_size;

    const dim3 blk(NTHREADS);

    // Phase 1: condition scores for all 16 rules in one batched launch
    const dim3 gridC(D_MODEL / BN, M_TOTAL / BM, NUM_RULES);
    rb_gemm<0><<<gridC, blk>>>(X, Wc, bc, nullptr, 0, 0);
    reduce_cond_kernel<<<(BATCH * NUM_RULES * D_MODEL + 255) / 256, 256>>>();

    // Phase 2: per rule: H = silu(X@Wa1+b); out (+)= (H@Wa2+b) * cond
    const dim3 grid(D_MODEL / BN, M_TOTAL / BM, 1);
    for (int rr = 0; rr < NUM_RULES; ++rr) {
        rb_gemm<1><<<grid, blk>>>(X, Wa1, ba1, nullptr, rr, 0);
        rb_gemm<2><<<grid, blk>>>(X, Wa2, ba2, out, rr, rr > 0);
    }
}